// round 8
// baseline (speedup 1.0000x reference)
#include <cuda_runtime.h>
#include <math.h>
#include <stdint.h>

// Problem dims (fixed by the dataset)
#define Bd 2
#define Td 2048
#define Cd 1024
#define Hd 16
#define Dd 64

// Scratch: qkv [B,T,3C] and attention output [B,T,C]
__device__ float g_qkv[(size_t)Bd * Td * 3 * Cd];
__device__ float g_att[(size_t)Bd * Td * Cd];

__device__ __forceinline__ uint32_t f2tf32(float x) {
    uint32_t r;
    asm("cvt.rna.tf32.f32 %0, %1;" : "=r"(r) : "f"(x));
    return r;
}

__device__ __forceinline__ void mma_tf32(float* c, const uint32_t* a,
                                         uint32_t b0, uint32_t b1) {
    asm volatile(
        "mma.sync.aligned.m16n8k8.row.col.f32.tf32.tf32.f32 "
        "{%0,%1,%2,%3}, {%4,%5,%6,%7}, {%8,%9}, {%0,%1,%2,%3};"
        : "+f"(c[0]), "+f"(c[1]), "+f"(c[2]), "+f"(c[3])
        : "r"(a[0]), "r"(a[1]), "r"(a[2]), "r"(a[3]), "r"(b0), "r"(b1));
}

// ldmatrix x4: four 8x8 b16 tiles (== four 8x4 b32 tiles)
__device__ __forceinline__ void ldmx4(uint32_t* r, const void* p) {
    uint32_t s = (uint32_t)__cvta_generic_to_shared(p);
    asm volatile("ldmatrix.sync.aligned.m8n8.x4.shared.b16 {%0,%1,%2,%3}, [%4];"
        : "=r"(r[0]), "=r"(r[1]), "=r"(r[2]), "=r"(r[3]) : "r"(s));
}

__device__ __forceinline__ void cp_async16(void* smem, const void* gmem) {
    uint32_t s = (uint32_t)__cvta_generic_to_shared(smem);
    asm volatile("cp.async.cg.shared.global [%0], [%1], 16;" :: "r"(s), "l"(gmem));
}
__device__ __forceinline__ void cp_commit() {
    asm volatile("cp.async.commit_group;");
}
__device__ __forceinline__ void cp_wait0() {
    asm volatile("cp.async.wait_group 0;");
}

// ---------------------------------------------------------------------------
// TF32 tensor-core GEMM + bias, cp.async double-buffered. (unchanged R6)
// ---------------------------------------------------------------------------
#define GBM 128
#define GBN 128
#define GBK 32

#define ASTR (GBK + 4)
#define BSTR (GBN + 8)
#define ASZ  (GBM * ASTR)
#define BSZ  (GBK * BSTR)

__global__ __launch_bounds__(256) void gemm_tf32_bias(
    const float* __restrict__ A, const float* __restrict__ B,
    const float* __restrict__ bias, float* __restrict__ C,
    int M, int N, int K)
{
    extern __shared__ __align__(16) float smem[];
    float* As = smem;
    float* Bs = smem + 2 * ASZ;

    const int tid  = threadIdx.x;
    const int warp = tid >> 5;
    const int lane = tid & 31;
    const int wm = warp >> 2;
    const int wn = warp & 3;
    const int g  = lane >> 2;
    const int cc = lane & 3;

    const int row0 = blockIdx.y * GBM;
    const int col0 = blockIdx.x * GBN;

    const float* Abase = A + (size_t)row0 * K;
    const float* Bbase = B + col0;

    const int ar  = tid >> 3;
    const int ac4 = (tid & 7) * 4;
    const int br  = tid >> 5;
    const int bc4 = (tid & 31) * 4;

    const int lm_row = lane & 7;
    const int lm_r8  = (lane >> 3) & 1;
    const int lm_c4  = (lane >> 4) * 4;

    float acc[4][4][4];
    #pragma unroll
    for (int mt = 0; mt < 4; mt++)
        #pragma unroll
        for (int nt = 0; nt < 4; nt++)
            #pragma unroll
            for (int q = 0; q < 4; q++) acc[mt][nt][q] = 0.0f;

    #pragma unroll
    for (int i = 0; i < 4; i++)
        cp_async16(&As[(ar + i * 32) * ASTR + ac4],
                   Abase + (size_t)(ar + i * 32) * K + ac4);
    #pragma unroll
    for (int i = 0; i < 4; i++)
        cp_async16(&Bs[(br + i * 8) * BSTR + bc4],
                   Bbase + (size_t)(br + i * 8) * N + bc4);
    cp_commit();

    int buf = 0;
    for (int k0 = 0; k0 < K; k0 += GBK) {
        cp_wait0();
        __syncthreads();

        float* Ab = As + buf * ASZ;
        float* Bb = Bs + buf * BSZ;
        #pragma unroll
        for (int i = 0; i < 4; i++) {
            float4* p = reinterpret_cast<float4*>(&Ab[(ar + i * 32) * ASTR + ac4]);
            float4 v = *p;
            v.x = __uint_as_float(f2tf32(v.x));
            v.y = __uint_as_float(f2tf32(v.y));
            v.z = __uint_as_float(f2tf32(v.z));
            v.w = __uint_as_float(f2tf32(v.w));
            *p = v;
        }
        #pragma unroll
        for (int i = 0; i < 4; i++) {
            float4* p = reinterpret_cast<float4*>(&Bb[(br + i * 8) * BSTR + bc4]);
            float4 v = *p;
            v.x = __uint_as_float(f2tf32(v.x));
            v.y = __uint_as_float(f2tf32(v.y));
            v.z = __uint_as_float(f2tf32(v.z));
            v.w = __uint_as_float(f2tf32(v.w));
            *p = v;
        }

        if (k0 + GBK < K) {
            const int nb = buf ^ 1;
            #pragma unroll
            for (int i = 0; i < 4; i++)
                cp_async16(&As[nb * ASZ + (ar + i * 32) * ASTR + ac4],
                           Abase + (size_t)(ar + i * 32) * K + k0 + GBK + ac4);
            #pragma unroll
            for (int i = 0; i < 4; i++)
                cp_async16(&Bs[nb * BSZ + (br + i * 8) * BSTR + bc4],
                           Bbase + (size_t)(k0 + GBK + br + i * 8) * N + bc4);
            cp_commit();
        }
        __syncthreads();

        #pragma unroll
        for (int kk = 0; kk < GBK / 8; kk++) {
            const int kc = kk * 8 + cc;
            uint32_t a[4][4];
            #pragma unroll
            for (int mt = 0; mt < 4; mt++) {
                int r = wm * 64 + mt * 16 + lm_row + lm_r8 * 8;
                ldmx4(a[mt], &Ab[r * ASTR + kk * 8 + lm_c4]);
            }
            uint32_t b[4][2];
            #pragma unroll
            for (int nt = 0; nt < 4; nt++) {
                int n = wn * 32 + nt * 8 + g;
                b[nt][0] = __float_as_uint(Bb[kc * BSTR + n]);
                b[nt][1] = __float_as_uint(Bb[(kc + 4) * BSTR + n]);
            }
            #pragma unroll
            for (int mt = 0; mt < 4; mt++)
                #pragma unroll
                for (int nt = 0; nt < 4; nt++)
                    mma_tf32(acc[mt][nt], a[mt], b[nt][0], b[nt][1]);
        }
        buf ^= 1;
    }

    #pragma unroll
    for (int mt = 0; mt < 4; mt++) {
        int r = row0 + wm * 64 + mt * 16 + g;
        #pragma unroll
        for (int nt = 0; nt < 4; nt++) {
            int n = col0 + wn * 32 + nt * 8 + cc * 2;
            float2 bb = *reinterpret_cast<const float2*>(bias + n);
            float2 o0, o1;
            o0.x = acc[mt][nt][0] + bb.x;
            o0.y = acc[mt][nt][1] + bb.y;
            o1.x = acc[mt][nt][2] + bb.x;
            o1.y = acc[mt][nt][3] + bb.y;
            *reinterpret_cast<float2*>(C + (size_t)r * N + n)       = o0;
            *reinterpret_cast<float2*>(C + (size_t)(r + 8) * N + n) = o1;
        }
    }
}

// ---------------------------------------------------------------------------
// Tensor-core causal flash attention (tf32, FA2).
// 256 threads = 8 warps x 16 query rows. cp.async double-buffered K/V with
// in-place tf32 cvt prepass. PV via per-warp SMEM P-tile + ldmatrix (no shfl).
// Exact skipping of fully-masked n-tiles. Reversed qt for load balance.
//
// TWO ldmatrix lane-address schemes (the R7 bug was conflating them):
//   K b-frag x4 : 4 matrices side-by-side in k  -> col = (lane>>3)*4
//   P a-frag x4 : 2x2 matrices in m x k         -> row += ((lane>>3)&1)*8,
//                                                  col  = (lane>>4)*4
// ---------------------------------------------------------------------------
#define AQ  128
#define AKV 64
#define KSTR 68   // 272B rows: 16B-aligned -> ldmatrix clean
#define VSTR 72   // LDS b-frag: bank = 8cc+g, bijective
#define PSTR 68

#define KTILE (AKV * KSTR)
#define VTILE (AKV * VSTR)
#define ATT_SMEM_FLOATS (2 * KTILE + 2 * VTILE + 8 * 16 * PSTR)

__global__ __launch_bounds__(256) void attn_mma_kernel()
{
    extern __shared__ __align__(16) float sm[];
    float* Kst = sm;                           // [2][AKV][KSTR]
    float* Vst = sm + 2 * KTILE;               // [2][AKV][VSTR]
    float* Pst = sm + 2 * KTILE + 2 * VTILE;   // [8][16][PSTR]

    const int qt   = (int)gridDim.x - 1 - (int)blockIdx.x;  // long blocks first
    const int bh   = blockIdx.y;
    const int b    = bh >> 4;
    const int h    = bh & 15;
    const int tid  = threadIdx.x;
    const int warp = tid >> 5;
    const int lane = tid & 31;
    const int g    = lane >> 2;
    const int cc   = lane & 3;

    const int q0      = qt * AQ;
    const int rowbase = q0 + warp * 16;
    const float* qkv_b = g_qkv + (size_t)b * Td * 3 * Cd;

    // staging coordinates
    const int sr  = tid >> 4;          // +16 per i
    const int sc4 = (tid & 15) * 4;

    // ldmatrix lane addressing — a-frag (P) scheme
    const int lm_row = lane & 7;
    const int lm_r8  = (lane >> 3) & 1;
    const int lm_c4  = (lane >> 4) * 4;
    // ldmatrix lane addressing — b-frag (K) scheme
    const int kb_c4  = (lane >> 3) * 4;   // {0,4,8,12}

    const int ntiles = (q0 + AQ) / AKV;

    // ---- prologue: issue stage 0 (raw fp32) ----
    #pragma unroll
    for (int i = 0; i < 4; i++) {
        const float* src = qkv_b + (size_t)(sr + i * 16) * 3 * Cd + h * Dd;
        cp_async16(&Kst[(sr + i * 16) * KSTR + sc4], src + Cd + sc4);
        cp_async16(&Vst[(sr + i * 16) * VSTR + sc4], src + 2 * Cd + sc4);
    }
    cp_commit();

    // ---- Q a-fragments, hi/lo tf32 split, pre-scaled by 1/sqrt(D) ----
    uint32_t qh[8][4], ql[8][4];
    {
        const float scale = 0.125f;
        const float* r0p = qkv_b + (size_t)(rowbase + g) * 3 * Cd + h * Dd;
        const float* r1p = qkv_b + (size_t)(rowbase + g + 8) * 3 * Cd + h * Dd;
        #pragma unroll
        for (int ks = 0; ks < 8; ks++) {
            float v[4];
            v[0] = r0p[ks * 8 + cc]     * scale;
            v[1] = r1p[ks * 8 + cc]     * scale;
            v[2] = r0p[ks * 8 + cc + 4] * scale;
            v[3] = r1p[ks * 8 + cc + 4] * scale;
            #pragma unroll
            for (int r = 0; r < 4; r++) {
                uint32_t hi = f2tf32(v[r]);
                qh[ks][r] = hi;
                ql[ks][r] = f2tf32(v[r] - __uint_as_float(hi));
            }
        }
    }

    float oc[8][4];
    #pragma unroll
    for (int nt = 0; nt < 8; nt++)
        #pragma unroll
        for (int r = 0; r < 4; r++) oc[nt][r] = 0.0f;

    float m0 = -INFINITY, m1 = -INFINITY, l0 = 0.0f, l1 = 0.0f;

    const unsigned FULL = 0xffffffffu;
    float* Pw = Pst + warp * 16 * PSTR;

    for (int kt = 0; kt < ntiles; kt++) {
        const int kv0 = kt * AKV;
        const int st  = kt & 1;
        float* Kb = Kst + st * KTILE;
        float* Vb = Vst + st * VTILE;

        cp_wait0();
        __syncthreads();   // stage kt landed; everyone done reading stage kt-1

        // ---- prepass: tf32-cvt this thread's staged elements in place ----
        #pragma unroll
        for (int i = 0; i < 4; i++) {
            float4* p = reinterpret_cast<float4*>(&Kb[(sr + i * 16) * KSTR + sc4]);
            float4 v = *p;
            v.x = __uint_as_float(f2tf32(v.x));
            v.y = __uint_as_float(f2tf32(v.y));
            v.z = __uint_as_float(f2tf32(v.z));
            v.w = __uint_as_float(f2tf32(v.w));
            *p = v;
        }
        #pragma unroll
        for (int i = 0; i < 4; i++) {
            float4* p = reinterpret_cast<float4*>(&Vb[(sr + i * 16) * VSTR + sc4]);
            float4 v = *p;
            v.x = __uint_as_float(f2tf32(v.x));
            v.y = __uint_as_float(f2tf32(v.y));
            v.z = __uint_as_float(f2tf32(v.z));
            v.w = __uint_as_float(f2tf32(v.w));
            *p = v;
        }

        // issue stage kt+1 into the other buffer (overlaps compute below)
        if (kt + 1 < ntiles) {
            const int ns = st ^ 1;
            const int nkv = kv0 + AKV;
            #pragma unroll
            for (int i = 0; i < 4; i++) {
                const float* src = qkv_b + (size_t)(nkv + sr + i * 16) * 3 * Cd + h * Dd;
                cp_async16(&Kst[ns * KTILE + (sr + i * 16) * KSTR + sc4], src + Cd + sc4);
                cp_async16(&Vst[ns * VTILE + (sr + i * 16) * VSTR + sc4], src + 2 * Cd + sc4);
            }
            cp_commit();
        }
        __syncthreads();   // converted tiles visible

        if (kv0 <= rowbase + 15) {
            // n-tiles with any causally-valid key
            const int nt_lim = min(8, ((rowbase + 15 - kv0) >> 3) + 1);

            // ---- S = Q @ K^T (hi + lo), K frags via ldmatrix (b-frag scheme) ----
            float sc[8][4];
            for (int nt = 0; nt < nt_lim; nt++) {
                sc[nt][0] = sc[nt][1] = sc[nt][2] = sc[nt][3] = 0.0f;
                #pragma unroll
                for (int kp = 0; kp < 4; kp++) {
                    uint32_t kb[4];
                    ldmx4(kb, &Kb[(nt * 8 + lm_row) * KSTR + kp * 16 + kb_c4]);
                    mma_tf32(sc[nt], qh[2 * kp],     kb[0], kb[1]);
                    mma_tf32(sc[nt], ql[2 * kp],     kb[0], kb[1]);
                    mma_tf32(sc[nt], qh[2 * kp + 1], kb[2], kb[3]);
                    mma_tf32(sc[nt], ql[2 * kp + 1], kb[2], kb[3]);
                }
            }

            // ---- causal element mask (diagonal-overlapping tiles) ----
            if (kv0 + AKV - 1 > rowbase) {
                const int r0 = rowbase + g;
                const int r1 = r0 + 8;
                for (int nt = 0; nt < nt_lim; nt++) {
                    int key = kv0 + nt * 8 + 2 * cc;
                    if (key     > r0) sc[nt][0] = -1e30f;
                    if (key + 1 > r0) sc[nt][1] = -1e30f;
                    if (key     > r1) sc[nt][2] = -1e30f;
                    if (key + 1 > r1) sc[nt][3] = -1e30f;
                }
            }

            // ---- online softmax ----
            float rm0 = -1e30f, rm1 = -1e30f;
            for (int nt = 0; nt < nt_lim; nt++) {
                rm0 = fmaxf(rm0, fmaxf(sc[nt][0], sc[nt][1]));
                rm1 = fmaxf(rm1, fmaxf(sc[nt][2], sc[nt][3]));
            }
            rm0 = fmaxf(rm0, __shfl_xor_sync(FULL, rm0, 1));
            rm0 = fmaxf(rm0, __shfl_xor_sync(FULL, rm0, 2));
            rm1 = fmaxf(rm1, __shfl_xor_sync(FULL, rm1, 1));
            rm1 = fmaxf(rm1, __shfl_xor_sync(FULL, rm1, 2));

            const float mn0 = fmaxf(m0, rm0);
            const float mn1 = fmaxf(m1, rm1);
            const float e0  = __expf(m0 - mn0);
            const float e1  = __expf(m1 - mn1);
            m0 = mn0; m1 = mn1;

            float rs0 = 0.0f, rs1 = 0.0f;
            for (int nt = 0; nt < nt_lim; nt++) {
                sc[nt][0] = __expf(sc[nt][0] - mn0);
                sc[nt][1] = __expf(sc[nt][1] - mn0);
                sc[nt][2] = __expf(sc[nt][2] - mn1);
                sc[nt][3] = __expf(sc[nt][3] - mn1);
                rs0 += sc[nt][0] + sc[nt][1];
                rs1 += sc[nt][2] + sc[nt][3];

                // store tf32-rounded P to per-warp SMEM tile
                float2 p01, p23;
                p01.x = __uint_as_float(f2tf32(sc[nt][0]));
                p01.y = __uint_as_float(f2tf32(sc[nt][1]));
                p23.x = __uint_as_float(f2tf32(sc[nt][2]));
                p23.y = __uint_as_float(f2tf32(sc[nt][3]));
                *reinterpret_cast<float2*>(&Pw[g * PSTR + nt * 8 + 2 * cc])       = p01;
                *reinterpret_cast<float2*>(&Pw[(g + 8) * PSTR + nt * 8 + 2 * cc]) = p23;
            }
            rs0 += __shfl_xor_sync(FULL, rs0, 1);
            rs0 += __shfl_xor_sync(FULL, rs0, 2);
            rs1 += __shfl_xor_sync(FULL, rs1, 1);
            rs1 += __shfl_xor_sync(FULL, rs1, 2);

            l0 = l0 * e0 + rs0;
            l1 = l1 * e1 + rs1;

            #pragma unroll
            for (int nt = 0; nt < 8; nt++) {
                oc[nt][0] *= e0; oc[nt][1] *= e0;
                oc[nt][2] *= e1; oc[nt][3] *= e1;
            }

            __syncwarp();

            // ---- O += P @ V : a-frags via ldmatrix (a-frag scheme) ----
            for (int ks = 0; ks < nt_lim; ks++) {
                uint32_t pa[4];
                ldmx4(pa, &Pw[(lm_row + lm_r8 * 8) * PSTR + ks * 8 + lm_c4]);
                #pragma unroll
                for (int nt = 0; nt < 8; nt++) {
                    uint32_t vb0 = __float_as_uint(Vb[(ks * 8 + cc) * VSTR + nt * 8 + g]);
                    uint32_t vb1 = __float_as_uint(Vb[(ks * 8 + cc + 4) * VSTR + nt * 8 + g]);
                    mma_tf32(oc[nt], pa, vb0, vb1);
                }
            }
        }
    }

    // ---- epilogue: normalize, write y_att ----
    const float inv0 = 1.0f / l0;
    const float inv1 = 1.0f / l1;
    const int r0 = rowbase + g;
    float* dst0 = g_att + ((size_t)b * Td + r0) * Cd + h * Dd;
    float* dst1 = g_att + ((size_t)b * Td + r0 + 8) * Cd + h * Dd;
    #pragma unroll
    for (int nt = 0; nt < 8; nt++) {
        float2 o0, o1;
        o0.x = oc[nt][0] * inv0;
        o0.y = oc[nt][1] * inv0;
        o1.x = oc[nt][2] * inv1;
        o1.y = oc[nt][3] * inv1;
        *reinterpret_cast<float2*>(dst0 + nt * 8 + 2 * cc) = o0;
        *reinterpret_cast<float2*>(dst1 + nt * 8 + 2 * cc) = o1;
    }
}

// ---------------------------------------------------------------------------
// Launch
// ---------------------------------------------------------------------------
extern "C" void kernel_launch(void* const* d_in, const int* in_sizes, int n_in,
                              void* d_out, int out_size)
{
    const float* x      = (const float*)d_in[0];
    // d_in[1] = attn_mask: tril by construction; causality handled structurally
    const float* W_attn = (const float*)d_in[2];
    const float* b_attn = (const float*)d_in[3];
    const float* W_proj = (const float*)d_in[4];
    const float* b_proj = (const float*)d_in[5];
    float* out = (float*)d_out;

    float* qkv = nullptr;
    float* att = nullptr;
    cudaGetSymbolAddress((void**)&qkv, g_qkv);
    cudaGetSymbolAddress((void**)&att, g_att);

    const int M = Bd * Td;     // 4096
    const int GEMM_SMEM = (2 * ASZ + 2 * BSZ) * (int)sizeof(float);   // ~70 KB
    const int ATT_SMEM  = ATT_SMEM_FLOATS * (int)sizeof(float);       // ~104 KB

    static bool attr_set = false;
    if (!attr_set) {
        cudaFuncSetAttribute(gemm_tf32_bias,
                             cudaFuncAttributeMaxDynamicSharedMemorySize,
                             GEMM_SMEM);
        cudaFuncSetAttribute(attn_mma_kernel,
                             cudaFuncAttributeMaxDynamicSharedMemorySize,
                             ATT_SMEM);
        attr_set = true;
    }

    // 1) QKV = x @ W_attn + b_attn : [4096,1024] x [1024,3072]
    {
        dim3 grid((3 * Cd) / GBN, M / GBM);
        gemm_tf32_bias<<<grid, 256, GEMM_SMEM>>>(x, W_attn, b_attn, qkv, M, 3 * Cd, Cd);
    }
    // 2) causal attention per (b,h), tensor-core
    {
        dim3 grid(Td / AQ, Bd * Hd);
        attn_mma_kernel<<<grid, 256, ATT_SMEM>>>();
    }
    // 3) out = att @ W_proj + b_proj : [4096,1024] x [1024,1024]
    {
        dim3 grid(Cd / GBN, M / GBM);
        gemm_tf32_bias<<<grid, 256, GEMM_SMEM>>>(att, W_proj, b_proj, out, M, Cd, Cd);
    }
}

// round 9
// speedup vs baseline: 1.0284x; 1.0284x over previous
#include <cuda_runtime.h>
#include <math.h>
#include <stdint.h>

// Problem dims (fixed by the dataset)
#define Bd 2
#define Td 2048
#define Cd 1024
#define Hd 16
#define Dd 64

// Scratch: qkv [B,T,3C], attention output [B,T,C] (stored tf32-rounded),
// and tf32-pre-rounded copies of x / W_attn / W_proj.
__device__ float g_qkv[(size_t)Bd * Td * 3 * Cd];
__device__ float g_att[(size_t)Bd * Td * Cd];
__device__ float g_xr [(size_t)Bd * Td * Cd];
__device__ float g_war[(size_t)Cd * 3 * Cd];
__device__ float g_wpr[(size_t)Cd * Cd];

__device__ __forceinline__ uint32_t f2tf32(float x) {
    uint32_t r;
    asm("cvt.rna.tf32.f32 %0, %1;" : "=r"(r) : "f"(x));
    return r;
}

__device__ __forceinline__ void mma_tf32(float* c, const uint32_t* a,
                                         uint32_t b0, uint32_t b1) {
    asm volatile(
        "mma.sync.aligned.m16n8k8.row.col.f32.tf32.tf32.f32 "
        "{%0,%1,%2,%3}, {%4,%5,%6,%7}, {%8,%9}, {%0,%1,%2,%3};"
        : "+f"(c[0]), "+f"(c[1]), "+f"(c[2]), "+f"(c[3])
        : "r"(a[0]), "r"(a[1]), "r"(a[2]), "r"(a[3]), "r"(b0), "r"(b1));
}

// ldmatrix x4: four 8x8 b16 tiles (== four 8x4 b32 tiles)
__device__ __forceinline__ void ldmx4(uint32_t* r, const void* p) {
    uint32_t s = (uint32_t)__cvta_generic_to_shared(p);
    asm volatile("ldmatrix.sync.aligned.m8n8.x4.shared.b16 {%0,%1,%2,%3}, [%4];"
        : "=r"(r[0]), "=r"(r[1]), "=r"(r[2]), "=r"(r[3]) : "r"(s));
}

__device__ __forceinline__ void cp_async16(void* smem, const void* gmem) {
    uint32_t s = (uint32_t)__cvta_generic_to_shared(smem);
    asm volatile("cp.async.cg.shared.global [%0], [%1], 16;" :: "r"(s), "l"(gmem));
}
__device__ __forceinline__ void cp_commit() {
    asm volatile("cp.async.commit_group;");
}
__device__ __forceinline__ void cp_wait0() {
    asm volatile("cp.async.wait_group 0;");
}

// ---------------------------------------------------------------------------
// tf32 pre-rounding pass (float4 grid-stride)
// ---------------------------------------------------------------------------
__global__ __launch_bounds__(256) void round_tf32_kernel(
    float* __restrict__ dst, const float* __restrict__ src, int n4)
{
    int i = blockIdx.x * blockDim.x + threadIdx.x;
    if (i < n4) {
        float4 v = reinterpret_cast<const float4*>(src)[i];
        v.x = __uint_as_float(f2tf32(v.x));
        v.y = __uint_as_float(f2tf32(v.y));
        v.z = __uint_as_float(f2tf32(v.z));
        v.w = __uint_as_float(f2tf32(v.w));
        reinterpret_cast<float4*>(dst)[i] = v;
    }
}

// ---------------------------------------------------------------------------
// TF32 tensor-core GEMM + bias on PRE-ROUNDED inputs.
// cp.async double-buffered, ONE sync per k-block, no cvt anywhere.
// 128x128 block tile, BK=32, 8 warps (2x4), 64x32 warp tile, m16n8k8 mma.
// ---------------------------------------------------------------------------
#define GBM 128
#define GBN 128
#define GBK 32

#define ASTR (GBK + 4)
#define BSTR (GBN + 8)
#define ASZ  (GBM * ASTR)
#define BSZ  (GBK * BSTR)

__global__ __launch_bounds__(256) void gemm_tf32_bias(
    const float* __restrict__ A, const float* __restrict__ B,
    const float* __restrict__ bias, float* __restrict__ C,
    int M, int N, int K)
{
    extern __shared__ __align__(16) float smem[];
    float* As = smem;
    float* Bs = smem + 2 * ASZ;

    const int tid  = threadIdx.x;
    const int warp = tid >> 5;
    const int lane = tid & 31;
    const int wm = warp >> 2;
    const int wn = warp & 3;
    const int g  = lane >> 2;
    const int cc = lane & 3;

    const int row0 = blockIdx.y * GBM;
    const int col0 = blockIdx.x * GBN;

    const float* Abase = A + (size_t)row0 * K;
    const float* Bbase = B + col0;

    const int ar  = tid >> 3;
    const int ac4 = (tid & 7) * 4;
    const int br  = tid >> 5;
    const int bc4 = (tid & 31) * 4;

    // a-frag ldmatrix lane addressing (2x2 tiles in m x k)
    const int lm_row = lane & 7;
    const int lm_r8  = (lane >> 3) & 1;
    const int lm_c4  = (lane >> 4) * 4;

    float acc[4][4][4];
    #pragma unroll
    for (int mt = 0; mt < 4; mt++)
        #pragma unroll
        for (int nt = 0; nt < 4; nt++)
            #pragma unroll
            for (int q = 0; q < 4; q++) acc[mt][nt][q] = 0.0f;

    #pragma unroll
    for (int i = 0; i < 4; i++)
        cp_async16(&As[(ar + i * 32) * ASTR + ac4],
                   Abase + (size_t)(ar + i * 32) * K + ac4);
    #pragma unroll
    for (int i = 0; i < 4; i++)
        cp_async16(&Bs[(br + i * 8) * BSTR + bc4],
                   Bbase + (size_t)(br + i * 8) * N + bc4);
    cp_commit();

    int buf = 0;
    for (int k0 = 0; k0 < K; k0 += GBK) {
        cp_wait0();
        __syncthreads();   // stage visible; all warps done with other buffer

        if (k0 + GBK < K) {
            const int nb = buf ^ 1;
            #pragma unroll
            for (int i = 0; i < 4; i++)
                cp_async16(&As[nb * ASZ + (ar + i * 32) * ASTR + ac4],
                           Abase + (size_t)(ar + i * 32) * K + k0 + GBK + ac4);
            #pragma unroll
            for (int i = 0; i < 4; i++)
                cp_async16(&Bs[nb * BSZ + (br + i * 8) * BSTR + bc4],
                           Bbase + (size_t)(k0 + GBK + br + i * 8) * N + bc4);
            cp_commit();
        }

        const float* Ab = As + buf * ASZ;
        const float* Bb = Bs + buf * BSZ;
        #pragma unroll
        for (int kk = 0; kk < GBK / 8; kk++) {
            const int kc = kk * 8 + cc;
            uint32_t a[4][4];
            #pragma unroll
            for (int mt = 0; mt < 4; mt++) {
                int r = wm * 64 + mt * 16 + lm_row + lm_r8 * 8;
                ldmx4(a[mt], &Ab[r * ASTR + kk * 8 + lm_c4]);
            }
            uint32_t b[4][2];
            #pragma unroll
            for (int nt = 0; nt < 4; nt++) {
                int n = wn * 32 + nt * 8 + g;
                b[nt][0] = __float_as_uint(Bb[kc * BSTR + n]);
                b[nt][1] = __float_as_uint(Bb[(kc + 4) * BSTR + n]);
            }
            #pragma unroll
            for (int mt = 0; mt < 4; mt++)
                #pragma unroll
                for (int nt = 0; nt < 4; nt++)
                    mma_tf32(acc[mt][nt], a[mt], b[nt][0], b[nt][1]);
        }
        buf ^= 1;
    }

    #pragma unroll
    for (int mt = 0; mt < 4; mt++) {
        int r = row0 + wm * 64 + mt * 16 + g;
        #pragma unroll
        for (int nt = 0; nt < 4; nt++) {
            int n = col0 + wn * 32 + nt * 8 + cc * 2;
            float2 bb = *reinterpret_cast<const float2*>(bias + n);
            float2 o0, o1;
            o0.x = acc[mt][nt][0] + bb.x;
            o0.y = acc[mt][nt][1] + bb.y;
            o1.x = acc[mt][nt][2] + bb.x;
            o1.y = acc[mt][nt][3] + bb.y;
            *reinterpret_cast<float2*>(C + (size_t)r * N + n)       = o0;
            *reinterpret_cast<float2*>(C + (size_t)(r + 8) * N + n) = o1;
        }
    }
}

// ---------------------------------------------------------------------------
// Tensor-core causal flash attention (tf32, FA2) — R6 structure.
// 256 threads = 8 warps x 16 query rows; static SMEM; shuffle-based PV.
// Added: nt_lim skipping of fully-masked key-groups; reversed qt scheduling;
// epilogue stores tf32-rounded output (feeds pre-rounded proj GEMM).
// ---------------------------------------------------------------------------
#define AQ  128
#define AKV 64
#define KSTR 68   // 272B rows: 16B-aligned -> ldmatrix clean
#define VSTR 72   // LDS b-frag: bank = 8cc+g, bijective

__global__ __launch_bounds__(256) void attn_mma_kernel()
{
    __shared__ __align__(16) float Ks[AKV][KSTR];
    __shared__ __align__(16) float Vs[AKV][VSTR];

    const int qt   = (int)gridDim.x - 1 - (int)blockIdx.x;  // long blocks first
    const int bh   = blockIdx.y;
    const int b    = bh >> 4;
    const int h    = bh & 15;
    const int tid  = threadIdx.x;
    const int warp = tid >> 5;
    const int lane = tid & 31;
    const int g    = lane >> 2;
    const int cc   = lane & 3;

    const int q0      = qt * AQ;
    const int rowbase = q0 + warp * 16;
    const float* qkv_b = g_qkv + (size_t)b * Td * 3 * Cd;

    // b-frag (K) ldmatrix scheme: 4 matrices side-by-side in k
    const int lm_row = lane & 7;
    const int kb_c4  = (lane >> 3) * 4;   // {0,4,8,12}

    // ---- Q a-fragments, hi/lo tf32 split, pre-scaled by 1/sqrt(D) ----
    uint32_t qh[8][4], ql[8][4];
    {
        const float scale = 0.125f;
        const float* r0p = qkv_b + (size_t)(rowbase + g) * 3 * Cd + h * Dd;
        const float* r1p = qkv_b + (size_t)(rowbase + g + 8) * 3 * Cd + h * Dd;
        #pragma unroll
        for (int ks = 0; ks < 8; ks++) {
            float v[4];
            v[0] = r0p[ks * 8 + cc]     * scale;
            v[1] = r1p[ks * 8 + cc]     * scale;
            v[2] = r0p[ks * 8 + cc + 4] * scale;
            v[3] = r1p[ks * 8 + cc + 4] * scale;
            #pragma unroll
            for (int r = 0; r < 4; r++) {
                uint32_t hi = f2tf32(v[r]);
                qh[ks][r] = hi;
                ql[ks][r] = f2tf32(v[r] - __uint_as_float(hi));
            }
        }
    }

    float oc[8][4];
    #pragma unroll
    for (int nt = 0; nt < 8; nt++)
        #pragma unroll
        for (int r = 0; r < 4; r++) oc[nt][r] = 0.0f;

    float m0 = -INFINITY, m1 = -INFINITY, l0 = 0.0f, l1 = 0.0f;

    const int ntiles = (q0 + AQ) / AKV;
    const unsigned FULL = 0xffffffffu;
    const int src_a = (lane & ~3) | (cc >> 1);
    const int src_c = src_a + 2;

    for (int kt = 0; kt < ntiles; kt++) {
        const int kv0 = kt * AKV;
        __syncthreads();
        // Stage K and V tiles (tf32-rounded at store): 1024 float4 each
        #pragma unroll
        for (int i = 0; i < 4; i++) {
            int idx = tid + i * 256;
            int r   = idx >> 4;
            int c4  = (idx & 15) * 4;
            const float* src = qkv_b + (size_t)(kv0 + r) * 3 * Cd + h * Dd;
            float4 kv = *reinterpret_cast<const float4*>(src + Cd + c4);
            float4 vv = *reinterpret_cast<const float4*>(src + 2 * Cd + c4);
            float4 kw, vw;
            kw.x = __uint_as_float(f2tf32(kv.x));
            kw.y = __uint_as_float(f2tf32(kv.y));
            kw.z = __uint_as_float(f2tf32(kv.z));
            kw.w = __uint_as_float(f2tf32(kv.w));
            vw.x = __uint_as_float(f2tf32(vv.x));
            vw.y = __uint_as_float(f2tf32(vv.y));
            vw.z = __uint_as_float(f2tf32(vv.z));
            vw.w = __uint_as_float(f2tf32(vv.w));
            *reinterpret_cast<float4*>(&Ks[r][c4]) = kw;
            *reinterpret_cast<float4*>(&Vs[r][c4]) = vw;
        }
        __syncthreads();

        // Fully masked for this warp?
        if (kv0 > rowbase + 15) continue;

        // key-groups with any causally-valid key for this warp
        const int nt_lim = min(8, ((rowbase + 15 - kv0) >> 3) + 1);

        // ---- S = Q @ K^T (hi + lo), K frags via ldmatrix ----
        float sc[8][4];
        for (int nt = 0; nt < nt_lim; nt++) {
            sc[nt][0] = sc[nt][1] = sc[nt][2] = sc[nt][3] = 0.0f;
            #pragma unroll
            for (int kp = 0; kp < 4; kp++) {
                uint32_t kb[4];
                ldmx4(kb, &Ks[nt * 8 + lm_row][kp * 16 + kb_c4]);
                mma_tf32(sc[nt], qh[2 * kp],     kb[0], kb[1]);
                mma_tf32(sc[nt], ql[2 * kp],     kb[0], kb[1]);
                mma_tf32(sc[nt], qh[2 * kp + 1], kb[2], kb[3]);
                mma_tf32(sc[nt], ql[2 * kp + 1], kb[2], kb[3]);
            }
        }

        // ---- causal element mask (diagonal-overlapping tiles) ----
        if (kv0 + AKV - 1 > rowbase) {
            const int r0 = rowbase + g;
            const int r1 = r0 + 8;
            for (int nt = 0; nt < nt_lim; nt++) {
                int key = kv0 + nt * 8 + 2 * cc;
                if (key     > r0) sc[nt][0] = -1e30f;
                if (key + 1 > r0) sc[nt][1] = -1e30f;
                if (key     > r1) sc[nt][2] = -1e30f;
                if (key + 1 > r1) sc[nt][3] = -1e30f;
            }
        }

        // ---- online softmax ----
        float rm0 = -1e30f, rm1 = -1e30f;
        for (int nt = 0; nt < nt_lim; nt++) {
            rm0 = fmaxf(rm0, fmaxf(sc[nt][0], sc[nt][1]));
            rm1 = fmaxf(rm1, fmaxf(sc[nt][2], sc[nt][3]));
        }
        rm0 = fmaxf(rm0, __shfl_xor_sync(FULL, rm0, 1));
        rm0 = fmaxf(rm0, __shfl_xor_sync(FULL, rm0, 2));
        rm1 = fmaxf(rm1, __shfl_xor_sync(FULL, rm1, 1));
        rm1 = fmaxf(rm1, __shfl_xor_sync(FULL, rm1, 2));

        const float mn0 = fmaxf(m0, rm0);
        const float mn1 = fmaxf(m1, rm1);
        const float e0  = __expf(m0 - mn0);
        const float e1  = __expf(m1 - mn1);
        m0 = mn0; m1 = mn1;

        float rs0 = 0.0f, rs1 = 0.0f;
        for (int nt = 0; nt < nt_lim; nt++) {
            sc[nt][0] = __expf(sc[nt][0] - mn0);
            sc[nt][1] = __expf(sc[nt][1] - mn0);
            sc[nt][2] = __expf(sc[nt][2] - mn1);
            sc[nt][3] = __expf(sc[nt][3] - mn1);
            rs0 += sc[nt][0] + sc[nt][1];
            rs1 += sc[nt][2] + sc[nt][3];
        }
        rs0 += __shfl_xor_sync(FULL, rs0, 1);
        rs0 += __shfl_xor_sync(FULL, rs0, 2);
        rs1 += __shfl_xor_sync(FULL, rs1, 1);
        rs1 += __shfl_xor_sync(FULL, rs1, 2);

        l0 = l0 * e0 + rs0;
        l1 = l1 * e1 + rs1;

        #pragma unroll
        for (int nt = 0; nt < 8; nt++) {
            oc[nt][0] *= e0; oc[nt][1] *= e0;
            oc[nt][2] *= e1; oc[nt][3] *= e1;
        }

        // ---- O += P @ V : redistribute c-frag -> a-frag via shuffles ----
        for (int ks = 0; ks < nt_lim; ks++) {
            float y0 = __shfl_sync(FULL, sc[ks][0], src_a);
            float y1 = __shfl_sync(FULL, sc[ks][1], src_a);
            float z0 = __shfl_sync(FULL, sc[ks][0], src_c);
            float z1 = __shfl_sync(FULL, sc[ks][1], src_c);
            float w0 = __shfl_sync(FULL, sc[ks][2], src_a);
            float w1 = __shfl_sync(FULL, sc[ks][3], src_a);
            float x0 = __shfl_sync(FULL, sc[ks][2], src_c);
            float x1 = __shfl_sync(FULL, sc[ks][3], src_c);
            const bool odd = cc & 1;
            uint32_t pa[4];
            pa[0] = f2tf32(odd ? y1 : y0);
            pa[1] = f2tf32(odd ? w1 : w0);
            pa[2] = f2tf32(odd ? z1 : z0);
            pa[3] = f2tf32(odd ? x1 : x0);
            #pragma unroll
            for (int nt = 0; nt < 8; nt++) {
                uint32_t vb0 = __float_as_uint(Vs[ks * 8 + cc][nt * 8 + g]);
                uint32_t vb1 = __float_as_uint(Vs[ks * 8 + cc + 4][nt * 8 + g]);
                mma_tf32(oc[nt], pa, vb0, vb1);
            }
        }
    }

    // ---- epilogue: normalize, round to tf32, write y_att ----
    const float inv0 = 1.0f / l0;
    const float inv1 = 1.0f / l1;
    const int r0 = rowbase + g;
    float* dst0 = g_att + ((size_t)b * Td + r0) * Cd + h * Dd;
    float* dst1 = g_att + ((size_t)b * Td + r0 + 8) * Cd + h * Dd;
    #pragma unroll
    for (int nt = 0; nt < 8; nt++) {
        float2 o0, o1;
        o0.x = __uint_as_float(f2tf32(oc[nt][0] * inv0));
        o0.y = __uint_as_float(f2tf32(oc[nt][1] * inv0));
        o1.x = __uint_as_float(f2tf32(oc[nt][2] * inv1));
        o1.y = __uint_as_float(f2tf32(oc[nt][3] * inv1));
        *reinterpret_cast<float2*>(dst0 + nt * 8 + 2 * cc) = o0;
        *reinterpret_cast<float2*>(dst1 + nt * 8 + 2 * cc) = o1;
    }
}

// ---------------------------------------------------------------------------
// Launch
// ---------------------------------------------------------------------------
extern "C" void kernel_launch(void* const* d_in, const int* in_sizes, int n_in,
                              void* d_out, int out_size)
{
    const float* x      = (const float*)d_in[0];
    // d_in[1] = attn_mask: tril by construction; causality handled structurally
    const float* W_attn = (const float*)d_in[2];
    const float* b_attn = (const float*)d_in[3];
    const float* W_proj = (const float*)d_in[4];
    const float* b_proj = (const float*)d_in[5];
    float* out = (float*)d_out;

    float *qkv, *att, *xr, *war, *wpr;
    cudaGetSymbolAddress((void**)&qkv, g_qkv);
    cudaGetSymbolAddress((void**)&att, g_att);
    cudaGetSymbolAddress((void**)&xr,  g_xr);
    cudaGetSymbolAddress((void**)&war, g_war);
    cudaGetSymbolAddress((void**)&wpr, g_wpr);

    const int M = Bd * Td;     // 4096
    const int GEMM_SMEM = (2 * ASZ + 2 * BSZ) * (int)sizeof(float);   // ~70 KB

    static bool attr_set = false;
    if (!attr_set) {
        cudaFuncSetAttribute(gemm_tf32_bias,
                             cudaFuncAttributeMaxDynamicSharedMemorySize,
                             GEMM_SMEM);
        attr_set = true;
    }

    // 0) pre-round x and weights to tf32
    {
        int n4x = (M * Cd) / 4;              // 1,048,576
        int n4a = (Cd * 3 * Cd) / 4;         //   786,432
        int n4p = (Cd * Cd) / 4;             //   262,144
        round_tf32_kernel<<<(n4x + 255) / 256, 256>>>(xr,  x,      n4x);
        round_tf32_kernel<<<(n4a + 255) / 256, 256>>>(war, W_attn, n4a);
        round_tf32_kernel<<<(n4p + 255) / 256, 256>>>(wpr, W_proj, n4p);
    }

    // 1) QKV = xr @ war + b_attn : [4096,1024] x [1024,3072]
    {
        dim3 grid((3 * Cd) / GBN, M / GBM);
        gemm_tf32_bias<<<grid, 256, GEMM_SMEM>>>(xr, war, b_attn, qkv, M, 3 * Cd, Cd);
    }
    // 2) causal attention per (b,h), tensor-core (writes tf32-rounded att)
    {
        dim3 grid(Td / AQ, Bd * Hd);
        attn_mma_kernel<<<grid, 256>>>();
    }
    // 3) out = att @ wpr + b_proj : [4096,1024] x [1024,1024]
    {
        dim3 grid(Cd / GBN, M / GBM);
        gemm_tf32_bias<<<grid, 256, GEMM_SMEM>>>(att, wpr, b_proj, out, M, Cd, Cd);
    }
}

// round 10
// speedup vs baseline: 1.2479x; 1.2135x over previous
#include <cuda_runtime.h>
#include <math.h>
#include <stdint.h>

// Problem dims (fixed by the dataset)
#define Bd 2
#define Td 2048
#define Cd 1024
#define Hd 16
#define Dd 64

// Scratch: qkv [B,T,3C] (tf32-rounded by GEMM epilogue), attention output
// [B,T,C] (tf32-rounded), and tf32 copies of x / W_attn / W_proj.
__device__ float g_qkv[(size_t)Bd * Td * 3 * Cd];
__device__ float g_att[(size_t)Bd * Td * Cd];
__device__ float g_xr [(size_t)Bd * Td * Cd];
__device__ float g_war[(size_t)Cd * 3 * Cd];
__device__ float g_wpr[(size_t)Cd * Cd];

__device__ __forceinline__ uint32_t f2tf32(float x) {
    uint32_t r;
    asm("cvt.rna.tf32.f32 %0, %1;" : "=r"(r) : "f"(x));
    return r;
}

__device__ __forceinline__ void mma_tf32(float* c, const uint32_t* a,
                                         uint32_t b0, uint32_t b1) {
    asm volatile(
        "mma.sync.aligned.m16n8k8.row.col.f32.tf32.tf32.f32 "
        "{%0,%1,%2,%3}, {%4,%5,%6,%7}, {%8,%9}, {%0,%1,%2,%3};"
        : "+f"(c[0]), "+f"(c[1]), "+f"(c[2]), "+f"(c[3])
        : "r"(a[0]), "r"(a[1]), "r"(a[2]), "r"(a[3]), "r"(b0), "r"(b1));
}

// ldmatrix x4: four 8x8 b16 tiles (== four 8x4 b32 tiles)
__device__ __forceinline__ void ldmx4(uint32_t* r, const void* p) {
    uint32_t s = (uint32_t)__cvta_generic_to_shared(p);
    asm volatile("ldmatrix.sync.aligned.m8n8.x4.shared.b16 {%0,%1,%2,%3}, [%4];"
        : "=r"(r[0]), "=r"(r[1]), "=r"(r[2]), "=r"(r[3]) : "r"(s));
}

__device__ __forceinline__ void cp_async16(void* smem, const void* gmem) {
    uint32_t s = (uint32_t)__cvta_generic_to_shared(smem);
    asm volatile("cp.async.cg.shared.global [%0], [%1], 16;" :: "r"(s), "l"(gmem));
}
__device__ __forceinline__ void cp_commit() {
    asm volatile("cp.async.commit_group;");
}
__device__ __forceinline__ void cp_wait0() {
    asm volatile("cp.async.wait_group 0;");
}

// ---------------------------------------------------------------------------
// Fused tf32 pre-rounding: x, W_attn, W_proj in ONE launch.
// ---------------------------------------------------------------------------
__global__ __launch_bounds__(256) void round3_kernel(
    float* __restrict__ dx, const float* __restrict__ sx, int nx,
    float* __restrict__ da, const float* __restrict__ sa, int na,
    float* __restrict__ dp, const float* __restrict__ sp, int np)
{
    int i = blockIdx.x * blockDim.x + threadIdx.x;
    const float4* s;
    float4* d;
    int j;
    if (i < nx)           { s = (const float4*)sx; d = (float4*)dx; j = i; }
    else if (i < nx + na) { s = (const float4*)sa; d = (float4*)da; j = i - nx; }
    else if (i < nx + na + np) { s = (const float4*)sp; d = (float4*)dp; j = i - nx - na; }
    else return;
    float4 v = s[j];
    v.x = __uint_as_float(f2tf32(v.x));
    v.y = __uint_as_float(f2tf32(v.y));
    v.z = __uint_as_float(f2tf32(v.z));
    v.w = __uint_as_float(f2tf32(v.w));
    d[j] = v;
}

// ---------------------------------------------------------------------------
// TF32 tensor-core GEMM + bias on PRE-ROUNDED inputs.
// cp.async double-buffered, ONE sync per k-block, no cvt in the mainloop.
// round_out != 0: epilogue rounds C to tf32 (producer-rounding for consumers).
// ---------------------------------------------------------------------------
#define GBM 128
#define GBN 128
#define GBK 32

#define ASTR (GBK + 4)
#define BSTR (GBN + 8)
#define ASZ  (GBM * ASTR)
#define BSZ  (GBK * BSTR)

__global__ __launch_bounds__(256) void gemm_tf32_bias(
    const float* __restrict__ A, const float* __restrict__ B,
    const float* __restrict__ bias, float* __restrict__ C,
    int M, int N, int K, int round_out)
{
    extern __shared__ __align__(16) float smem[];
    float* As = smem;
    float* Bs = smem + 2 * ASZ;

    const int tid  = threadIdx.x;
    const int warp = tid >> 5;
    const int lane = tid & 31;
    const int wm = warp >> 2;
    const int wn = warp & 3;
    const int g  = lane >> 2;
    const int cc = lane & 3;

    const int row0 = blockIdx.y * GBM;
    const int col0 = blockIdx.x * GBN;

    const float* Abase = A + (size_t)row0 * K;
    const float* Bbase = B + col0;

    const int ar  = tid >> 3;
    const int ac4 = (tid & 7) * 4;
    const int br  = tid >> 5;
    const int bc4 = (tid & 31) * 4;

    const int lm_row = lane & 7;
    const int lm_r8  = (lane >> 3) & 1;
    const int lm_c4  = (lane >> 4) * 4;

    float acc[4][4][4];
    #pragma unroll
    for (int mt = 0; mt < 4; mt++)
        #pragma unroll
        for (int nt = 0; nt < 4; nt++)
            #pragma unroll
            for (int q = 0; q < 4; q++) acc[mt][nt][q] = 0.0f;

    #pragma unroll
    for (int i = 0; i < 4; i++)
        cp_async16(&As[(ar + i * 32) * ASTR + ac4],
                   Abase + (size_t)(ar + i * 32) * K + ac4);
    #pragma unroll
    for (int i = 0; i < 4; i++)
        cp_async16(&Bs[(br + i * 8) * BSTR + bc4],
                   Bbase + (size_t)(br + i * 8) * N + bc4);
    cp_commit();

    int buf = 0;
    for (int k0 = 0; k0 < K; k0 += GBK) {
        cp_wait0();
        __syncthreads();

        if (k0 + GBK < K) {
            const int nb = buf ^ 1;
            #pragma unroll
            for (int i = 0; i < 4; i++)
                cp_async16(&As[nb * ASZ + (ar + i * 32) * ASTR + ac4],
                           Abase + (size_t)(ar + i * 32) * K + k0 + GBK + ac4);
            #pragma unroll
            for (int i = 0; i < 4; i++)
                cp_async16(&Bs[nb * BSZ + (br + i * 8) * BSTR + bc4],
                           Bbase + (size_t)(k0 + GBK + br + i * 8) * N + bc4);
            cp_commit();
        }

        const float* Ab = As + buf * ASZ;
        const float* Bb = Bs + buf * BSZ;
        #pragma unroll
        for (int kk = 0; kk < GBK / 8; kk++) {
            const int kc = kk * 8 + cc;
            uint32_t a[4][4];
            #pragma unroll
            for (int mt = 0; mt < 4; mt++) {
                int r = wm * 64 + mt * 16 + lm_row + lm_r8 * 8;
                ldmx4(a[mt], &Ab[r * ASTR + kk * 8 + lm_c4]);
            }
            uint32_t b[4][2];
            #pragma unroll
            for (int nt = 0; nt < 4; nt++) {
                int n = wn * 32 + nt * 8 + g;
                b[nt][0] = __float_as_uint(Bb[kc * BSTR + n]);
                b[nt][1] = __float_as_uint(Bb[(kc + 4) * BSTR + n]);
            }
            #pragma unroll
            for (int mt = 0; mt < 4; mt++)
                #pragma unroll
                for (int nt = 0; nt < 4; nt++)
                    mma_tf32(acc[mt][nt], a[mt], b[nt][0], b[nt][1]);
        }
        buf ^= 1;
    }

    #pragma unroll
    for (int mt = 0; mt < 4; mt++) {
        int r = row0 + wm * 64 + mt * 16 + g;
        #pragma unroll
        for (int nt = 0; nt < 4; nt++) {
            int n = col0 + wn * 32 + nt * 8 + cc * 2;
            float2 bb = *reinterpret_cast<const float2*>(bias + n);
            float2 o0, o1;
            o0.x = acc[mt][nt][0] + bb.x;
            o0.y = acc[mt][nt][1] + bb.y;
            o1.x = acc[mt][nt][2] + bb.x;
            o1.y = acc[mt][nt][3] + bb.y;
            if (round_out) {
                o0.x = __uint_as_float(f2tf32(o0.x));
                o0.y = __uint_as_float(f2tf32(o0.y));
                o1.x = __uint_as_float(f2tf32(o1.x));
                o1.y = __uint_as_float(f2tf32(o1.y));
            }
            *reinterpret_cast<float2*>(C + (size_t)r * N + n)       = o0;
            *reinterpret_cast<float2*>(C + (size_t)(r + 8) * N + n) = o1;
        }
    }
}

// ---------------------------------------------------------------------------
// Tensor-core causal flash attention (tf32, FA2).
// qkv is ALREADY tf32-rounded -> staging is pure cp.async double-buffer
// (no cvt); Q is single tf32 (q*0.125 exact: x2^-3 preserves mantissa).
// 256 threads = 8 warps x 16 query rows; shuffle-based PV; nt_lim skip;
// reversed qt. Epilogue writes tf32-rounded att for the proj GEMM.
// ---------------------------------------------------------------------------
#define AQ  128
#define AKV 64
#define KSTR 68   // 272B rows: 16B-aligned -> ldmatrix clean
#define VSTR 72   // LDS b-frag: bank = 8cc+g, bijective

#define KTILE (AKV * KSTR)
#define VTILE (AKV * VSTR)
#define ATT_SMEM_FLOATS (2 * KTILE + 2 * VTILE)

__global__ __launch_bounds__(256) void attn_mma_kernel()
{
    extern __shared__ __align__(16) float sm[];
    float* Kst = sm;               // [2][AKV][KSTR]
    float* Vst = sm + 2 * KTILE;   // [2][AKV][VSTR]

    const int qt   = (int)gridDim.x - 1 - (int)blockIdx.x;  // long blocks first
    const int bh   = blockIdx.y;
    const int b    = bh >> 4;
    const int h    = bh & 15;
    const int tid  = threadIdx.x;
    const int warp = tid >> 5;
    const int lane = tid & 31;
    const int g    = lane >> 2;
    const int cc   = lane & 3;

    const int q0      = qt * AQ;
    const int rowbase = q0 + warp * 16;
    const float* qkv_b = g_qkv + (size_t)b * Td * 3 * Cd;

    // staging coordinates
    const int sr  = tid >> 4;          // 0..15, +16 per i
    const int sc4 = (tid & 15) * 4;

    // b-frag (K) ldmatrix scheme: 4 matrices side-by-side in k
    const int lm_row = lane & 7;
    const int kb_c4  = (lane >> 3) * 4;   // {0,4,8,12}

    const int ntiles = (q0 + AQ) / AKV;

    // ---- prologue: issue K/V stage 0 (already tf32) ----
    #pragma unroll
    for (int i = 0; i < 4; i++) {
        const float* src = qkv_b + (size_t)(sr + i * 16) * 3 * Cd + h * Dd;
        cp_async16(&Kst[(sr + i * 16) * KSTR + sc4], src + Cd + sc4);
        cp_async16(&Vst[(sr + i * 16) * VSTR + sc4], src + 2 * Cd + sc4);
    }
    cp_commit();

    // ---- Q a-fragments: already tf32; *0.125 exact ----
    uint32_t qh[8][4];
    {
        const float scale = 0.125f;
        const float* r0p = qkv_b + (size_t)(rowbase + g) * 3 * Cd + h * Dd;
        const float* r1p = qkv_b + (size_t)(rowbase + g + 8) * 3 * Cd + h * Dd;
        #pragma unroll
        for (int ks = 0; ks < 8; ks++) {
            qh[ks][0] = __float_as_uint(r0p[ks * 8 + cc]     * scale);
            qh[ks][1] = __float_as_uint(r1p[ks * 8 + cc]     * scale);
            qh[ks][2] = __float_as_uint(r0p[ks * 8 + cc + 4] * scale);
            qh[ks][3] = __float_as_uint(r1p[ks * 8 + cc + 4] * scale);
        }
    }

    float oc[8][4];
    #pragma unroll
    for (int nt = 0; nt < 8; nt++)
        #pragma unroll
        for (int r = 0; r < 4; r++) oc[nt][r] = 0.0f;

    float m0 = -INFINITY, m1 = -INFINITY, l0 = 0.0f, l1 = 0.0f;

    const unsigned FULL = 0xffffffffu;
    const int src_a = (lane & ~3) | (cc >> 1);
    const int src_c = src_a + 2;

    for (int kt = 0; kt < ntiles; kt++) {
        const int kv0 = kt * AKV;
        const int st  = kt & 1;
        const float* Kb = Kst + st * KTILE;
        const float* Vb = Vst + st * VTILE;

        cp_wait0();
        __syncthreads();   // stage kt landed; all warps done with stage kt-1

        // issue stage kt+1 into the other buffer (overlaps compute)
        if (kt + 1 < ntiles) {
            const int ns = st ^ 1;
            const int nkv = kv0 + AKV;
            #pragma unroll
            for (int i = 0; i < 4; i++) {
                const float* src = qkv_b + (size_t)(nkv + sr + i * 16) * 3 * Cd + h * Dd;
                cp_async16(&Kst[ns * KTILE + (sr + i * 16) * KSTR + sc4], src + Cd + sc4);
                cp_async16(&Vst[ns * VTILE + (sr + i * 16) * VSTR + sc4], src + 2 * Cd + sc4);
            }
            cp_commit();
        }

        // Fully masked for this warp?
        if (kv0 > rowbase + 15) continue;

        // key-groups with any causally-valid key for this warp
        const int nt_lim = min(8, ((rowbase + 15 - kv0) >> 3) + 1);

        // ---- S = Q @ K^T (single tf32), K frags via ldmatrix ----
        float sc[8][4];
        for (int nt = 0; nt < nt_lim; nt++) {
            sc[nt][0] = sc[nt][1] = sc[nt][2] = sc[nt][3] = 0.0f;
            #pragma unroll
            for (int kp = 0; kp < 4; kp++) {
                uint32_t kb[4];
                ldmx4(kb, &Kb[(nt * 8 + lm_row) * KSTR + kp * 16 + kb_c4]);
                mma_tf32(sc[nt], qh[2 * kp],     kb[0], kb[1]);
                mma_tf32(sc[nt], qh[2 * kp + 1], kb[2], kb[3]);
            }
        }

        // ---- causal element mask (diagonal-overlapping tiles) ----
        if (kv0 + AKV - 1 > rowbase) {
            const int r0 = rowbase + g;
            const int r1 = r0 + 8;
            for (int nt = 0; nt < nt_lim; nt++) {
                int key = kv0 + nt * 8 + 2 * cc;
                if (key     > r0) sc[nt][0] = -1e30f;
                if (key + 1 > r0) sc[nt][1] = -1e30f;
                if (key     > r1) sc[nt][2] = -1e30f;
                if (key + 1 > r1) sc[nt][3] = -1e30f;
            }
        }

        // ---- online softmax ----
        float rm0 = -1e30f, rm1 = -1e30f;
        for (int nt = 0; nt < nt_lim; nt++) {
            rm0 = fmaxf(rm0, fmaxf(sc[nt][0], sc[nt][1]));
            rm1 = fmaxf(rm1, fmaxf(sc[nt][2], sc[nt][3]));
        }
        rm0 = fmaxf(rm0, __shfl_xor_sync(FULL, rm0, 1));
        rm0 = fmaxf(rm0, __shfl_xor_sync(FULL, rm0, 2));
        rm1 = fmaxf(rm1, __shfl_xor_sync(FULL, rm1, 1));
        rm1 = fmaxf(rm1, __shfl_xor_sync(FULL, rm1, 2));

        const float mn0 = fmaxf(m0, rm0);
        const float mn1 = fmaxf(m1, rm1);
        const float e0  = __expf(m0 - mn0);
        const float e1  = __expf(m1 - mn1);
        m0 = mn0; m1 = mn1;

        float rs0 = 0.0f, rs1 = 0.0f;
        for (int nt = 0; nt < nt_lim; nt++) {
            sc[nt][0] = __expf(sc[nt][0] - mn0);
            sc[nt][1] = __expf(sc[nt][1] - mn0);
            sc[nt][2] = __expf(sc[nt][2] - mn1);
            sc[nt][3] = __expf(sc[nt][3] - mn1);
            rs0 += sc[nt][0] + sc[nt][1];
            rs1 += sc[nt][2] + sc[nt][3];
        }
        rs0 += __shfl_xor_sync(FULL, rs0, 1);
        rs0 += __shfl_xor_sync(FULL, rs0, 2);
        rs1 += __shfl_xor_sync(FULL, rs1, 1);
        rs1 += __shfl_xor_sync(FULL, rs1, 2);

        l0 = l0 * e0 + rs0;
        l1 = l1 * e1 + rs1;

        #pragma unroll
        for (int nt = 0; nt < 8; nt++) {
            oc[nt][0] *= e0; oc[nt][1] *= e0;
            oc[nt][2] *= e1; oc[nt][3] *= e1;
        }

        // ---- O += P @ V : redistribute c-frag -> a-frag via shuffles ----
        for (int ks = 0; ks < nt_lim; ks++) {
            float y0 = __shfl_sync(FULL, sc[ks][0], src_a);
            float y1 = __shfl_sync(FULL, sc[ks][1], src_a);
            float z0 = __shfl_sync(FULL, sc[ks][0], src_c);
            float z1 = __shfl_sync(FULL, sc[ks][1], src_c);
            float w0 = __shfl_sync(FULL, sc[ks][2], src_a);
            float w1 = __shfl_sync(FULL, sc[ks][3], src_a);
            float x0 = __shfl_sync(FULL, sc[ks][2], src_c);
            float x1 = __shfl_sync(FULL, sc[ks][3], src_c);
            const bool odd = cc & 1;
            uint32_t pa[4];
            pa[0] = f2tf32(odd ? y1 : y0);
            pa[1] = f2tf32(odd ? w1 : w0);
            pa[2] = f2tf32(odd ? z1 : z0);
            pa[3] = f2tf32(odd ? x1 : x0);
            #pragma unroll
            for (int nt = 0; nt < 8; nt++) {
                uint32_t vb0 = __float_as_uint(Vb[(ks * 8 + cc) * VSTR + nt * 8 + g]);
                uint32_t vb1 = __float_as_uint(Vb[(ks * 8 + cc + 4) * VSTR + nt * 8 + g]);
                mma_tf32(oc[nt], pa, vb0, vb1);
            }
        }
    }

    // ---- epilogue: normalize, round to tf32, write y_att ----
    const float inv0 = 1.0f / l0;
    const float inv1 = 1.0f / l1;
    const int r0 = rowbase + g;
    float* dst0 = g_att + ((size_t)b * Td + r0) * Cd + h * Dd;
    float* dst1 = g_att + ((size_t)b * Td + r0 + 8) * Cd + h * Dd;
    #pragma unroll
    for (int nt = 0; nt < 8; nt++) {
        float2 o0, o1;
        o0.x = __uint_as_float(f2tf32(oc[nt][0] * inv0));
        o0.y = __uint_as_float(f2tf32(oc[nt][1] * inv0));
        o1.x = __uint_as_float(f2tf32(oc[nt][2] * inv1));
        o1.y = __uint_as_float(f2tf32(oc[nt][3] * inv1));
        *reinterpret_cast<float2*>(dst0 + nt * 8 + 2 * cc) = o0;
        *reinterpret_cast<float2*>(dst1 + nt * 8 + 2 * cc) = o1;
    }
}

// ---------------------------------------------------------------------------
// Launch
// ---------------------------------------------------------------------------
extern "C" void kernel_launch(void* const* d_in, const int* in_sizes, int n_in,
                              void* d_out, int out_size)
{
    const float* x      = (const float*)d_in[0];
    // d_in[1] = attn_mask: tril by construction; causality handled structurally
    const float* W_attn = (const float*)d_in[2];
    const float* b_attn = (const float*)d_in[3];
    const float* W_proj = (const float*)d_in[4];
    const float* b_proj = (const float*)d_in[5];
    float* out = (float*)d_out;

    float *qkv, *att, *xr, *war, *wpr;
    cudaGetSymbolAddress((void**)&qkv, g_qkv);
    cudaGetSymbolAddress((void**)&att, g_att);
    cudaGetSymbolAddress((void**)&xr,  g_xr);
    cudaGetSymbolAddress((void**)&war, g_war);
    cudaGetSymbolAddress((void**)&wpr, g_wpr);

    const int M = Bd * Td;     // 4096
    const int GEMM_SMEM = (2 * ASZ + 2 * BSZ) * (int)sizeof(float);   // ~70 KB
    const int ATT_SMEM  = ATT_SMEM_FLOATS * (int)sizeof(float);       // ~70 KB

    static bool attr_set = false;
    if (!attr_set) {
        cudaFuncSetAttribute(gemm_tf32_bias,
                             cudaFuncAttributeMaxDynamicSharedMemorySize,
                             GEMM_SMEM);
        cudaFuncSetAttribute(attn_mma_kernel,
                             cudaFuncAttributeMaxDynamicSharedMemorySize,
                             ATT_SMEM);
        attr_set = true;
    }

    // 0) fused tf32 pre-round of x, W_attn, W_proj
    {
        int n4x = (M * Cd) / 4;
        int n4a = (Cd * 3 * Cd) / 4;
        int n4p = (Cd * Cd) / 4;
        int n4  = n4x + n4a + n4p;
        round3_kernel<<<(n4 + 255) / 256, 256>>>(xr, x, n4x, war, W_attn, n4a,
                                                 wpr, W_proj, n4p);
    }

    // 1) QKV = xr @ war + b_attn, epilogue rounds output to tf32
    {
        dim3 grid((3 * Cd) / GBN, M / GBM);
        gemm_tf32_bias<<<grid, 256, GEMM_SMEM>>>(xr, war, b_attn, qkv,
                                                 M, 3 * Cd, Cd, 1);
    }
    // 2) causal attention (tf32 qkv in, tf32-rounded att out)
    {
        dim3 grid(Td / AQ, Bd * Hd);
        attn_mma_kernel<<<grid, 256, ATT_SMEM>>>();
    }
    // 3) out = att @ wpr + b_proj (fp32 out, no rounding)
    {
        dim3 grid(Cd / GBN, M / GBM);
        gemm_tf32_bias<<<grid, 256, GEMM_SMEM>>>(att, wpr, b_proj, out,
                                                 M, Cd, Cd, 0);
    }
}